// round 6
// baseline (speedup 1.0000x reference)
#include <cuda_runtime.h>

#define N_NODES 10000
#define N_EDGES 160000
#define DIM     1280
#define D4      (DIM / 4)   // 320 float4 per row

// ---- scratch (device globals; zero at load, self-reset every launch) ----
__device__ float g_outw[N_NODES];
__device__ float g_q[N_NODES];
__device__ float g_ew[N_EDGES];   // overwritten every launch, no reset needed
__device__ float g_Csum;          // sum of all edge weights (C = N + Csum)
__device__ float g_S1[DIM];       // sum_s coef[s]*h0[s]
__device__ float g_msum[DIM];     // sum_s h0[s]
__device__ float g_v1[DIM];       // layer-1 weighted-mean output (fully overwritten)

__device__ __forceinline__ float edge_w(float x) {
    return 1.0f / (x * x + 1e-6f);
}
__device__ __forceinline__ void fma4(float4& a, float c, const float4& v) {
    a.x = fmaf(c, v.x, a.x); a.y = fmaf(c, v.y, a.y);
    a.z = fmaf(c, v.z, a.z); a.w = fmaf(c, v.w, a.w);
}
__device__ __forceinline__ void add4(float4& a, const float4& v) {
    a.x += v.x; a.y += v.y; a.z += v.z; a.w += v.w;
}

// ---------- kA: ew cache + outw[src] += ew + Csum ----------
__global__ void kA(const float* __restrict__ ef, const int* __restrict__ src) {
    int e = blockIdx.x * blockDim.x + threadIdx.x;
    float w = 0.f;
    if (e < N_EDGES) {
        w = edge_w(ef[e]);
        g_ew[e] = w;
        atomicAdd(&g_outw[src[e]], w);
    }
    // block-reduce w into one atomic (Csum = sum of all edge weights)
    #pragma unroll
    for (int o = 16; o; o >>= 1) w += __shfl_down_sync(0xffffffffu, w, o);
    __shared__ float sh[32];
    if (threadIdx.x < 32) sh[threadIdx.x] = 0.f;
    __syncthreads();
    if ((threadIdx.x & 31) == 0) sh[threadIdx.x >> 5] = w;
    __syncthreads();
    if (threadIdx.x < 32) {
        float v = sh[threadIdx.x];
        #pragma unroll
        for (int o = 16; o; o >>= 1) v += __shfl_down_sync(0xffffffffu, v, o);
        if (threadIdx.x == 0) atomicAdd(&g_Csum, v);
    }
}

// ---------- kB: q[src] += ew * (1 + outw[dst]) ----------
__global__ void kB(const int* __restrict__ src, const int* __restrict__ dst) {
    int e = blockIdx.x * blockDim.x + threadIdx.x;
    if (e < N_EDGES) {
        float w = g_ew[e];
        atomicAdd(&g_q[src[e]], w * (1.0f + g_outw[dst[e]]));
    }
}

// ---------- kC: dominant pass — weighted + plain column sums ----------
// 320 threads = one float4 slice per thread; 4-way row unroll for MLP.
__global__ void __launch_bounds__(D4) kC(const float* __restrict__ node) {
    const int t = threadIdx.x;
    const int stride = gridDim.x;
    const float4* __restrict__ h4 = (const float4*)node;
    float4 aw = make_float4(0.f, 0.f, 0.f, 0.f);
    float4 as = make_float4(0.f, 0.f, 0.f, 0.f);
    int s = blockIdx.x;
    for (; s + 3 * stride < N_NODES; s += 4 * stride) {
        int s0 = s, s1 = s + stride, s2 = s + 2 * stride, s3 = s + 3 * stride;
        float c0 = 1.0f + __ldg(&g_outw[s0]) + __ldg(&g_q[s0]);
        float c1 = 1.0f + __ldg(&g_outw[s1]) + __ldg(&g_q[s1]);
        float c2 = 1.0f + __ldg(&g_outw[s2]) + __ldg(&g_q[s2]);
        float c3 = 1.0f + __ldg(&g_outw[s3]) + __ldg(&g_q[s3]);
        float4 v0 = __ldg(&h4[(long)s0 * D4 + t]);
        float4 v1 = __ldg(&h4[(long)s1 * D4 + t]);
        float4 v2 = __ldg(&h4[(long)s2 * D4 + t]);
        float4 v3 = __ldg(&h4[(long)s3 * D4 + t]);
        fma4(aw, c0, v0); add4(as, v0);
        fma4(aw, c1, v1); add4(as, v1);
        fma4(aw, c2, v2); add4(as, v2);
        fma4(aw, c3, v3); add4(as, v3);
    }
    for (; s < N_NODES; s += stride) {
        float c = 1.0f + __ldg(&g_outw[s]) + __ldg(&g_q[s]);
        float4 v = __ldg(&h4[(long)s * D4 + t]);
        fma4(aw, c, v); add4(as, v);
    }
    int d = 4 * t;
    atomicAdd(&g_S1[d + 0], aw.x); atomicAdd(&g_S1[d + 1], aw.y);
    atomicAdd(&g_S1[d + 2], aw.z); atomicAdd(&g_S1[d + 3], aw.w);
    atomicAdd(&g_msum[d + 0], as.x); atomicAdd(&g_msum[d + 1], as.y);
    atomicAdd(&g_msum[d + 2], as.z); atomicAdd(&g_msum[d + 3], as.w);
}

// ---------- kMV1: v1 = (S1 @ W1^T + C*b1)/N ; resets outw,q ----------
__global__ void kMV1(const float* __restrict__ W1, const float* __restrict__ b1) {
    int gt = blockIdx.x * blockDim.x + threadIdx.x;
    int nt = gridDim.x * blockDim.x;
    // reset edge-phase scratch (not read in this kernel)
    for (int s = gt; s < N_NODES; s += nt) { g_outw[s] = 0.f; g_q[s] = 0.f; }

    int warp = gt >> 5;
    int lane = threadIdx.x & 31;
    if (warp >= DIM) return;
    const float4* __restrict__ row = (const float4*)(W1 + (long)warp * DIM);
    const float4* __restrict__ s1  = (const float4*)g_S1;
    float acc = 0.f;
    #pragma unroll
    for (int j = lane; j < D4; j += 32) {
        float4 w = __ldg(&row[j]);
        float4 s = s1[j];
        acc += w.x * s.x + w.y * s.y + w.z * s.z + w.w * s.w;
    }
    #pragma unroll
    for (int o = 16; o; o >>= 1) acc += __shfl_down_sync(0xffffffffu, acc, o);
    if (lane == 0) {
        const float invN = 1.0f / (float)N_NODES;
        float C = (float)N_NODES + g_Csum;
        g_v1[warp] = acc * invN + C * invN * __ldg(&b1[warp]);
    }
}

// ---------- kMV2: out = v1 @ W2^T + b2 + msum/N ; resets msum,S1,Csum ----------
__global__ void kMV2(const float* __restrict__ W2, const float* __restrict__ b2,
                     float* __restrict__ out) {
    int gt = blockIdx.x * blockDim.x + threadIdx.x;
    int nt = gridDim.x * blockDim.x;
    // reset S1 (consumed in kMV1) + Csum
    for (int d = gt; d < DIM; d += nt) g_S1[d] = 0.f;
    if (gt == 0) g_Csum = 0.f;

    int warp = gt >> 5;
    int lane = threadIdx.x & 31;
    if (warp >= DIM) return;
    const float4* __restrict__ row = (const float4*)(W2 + (long)warp * DIM);
    const float4* __restrict__ v1  = (const float4*)g_v1;
    float acc = 0.f;
    #pragma unroll
    for (int j = lane; j < D4; j += 32) {
        float4 w = __ldg(&row[j]);
        float4 v = v1[j];
        acc += w.x * v.x + w.y * v.y + w.z * v.z + w.w * v.w;
    }
    #pragma unroll
    for (int o = 16; o; o >>= 1) acc += __shfl_down_sync(0xffffffffu, acc, o);
    if (lane == 0) {
        const float invN = 1.0f / (float)N_NODES;
        out[warp] = acc + __ldg(&b2[warp]) + g_msum[warp] * invN;
        g_msum[warp] = 0.f;   // owner-warp reset after final read
    }
}

extern "C" void kernel_launch(void* const* d_in, const int* in_sizes, int n_in,
                              void* d_out, int out_size) {
    const float* node = (const float*)d_in[0];   // [N, D]
    const float* ef   = (const float*)d_in[1];   // [E]
    const int*   ei   = (const int*)  d_in[2];   // [2, E]
    const float* W1   = (const float*)d_in[3];
    const float* b1   = (const float*)d_in[4];
    const float* W2   = (const float*)d_in[5];
    const float* b2   = (const float*)d_in[6];
    float* out = (float*)d_out;

    const int* src = ei;
    const int* dst = ei + N_EDGES;

    kA<<<(N_EDGES + 255) / 256, 256>>>(ef, src);
    kB<<<(N_EDGES + 255) / 256, 256>>>(src, dst);
    kC<<<592, D4>>>(node);                               // ~4 blocks/SM, MLP>=4
    kMV1<<<(DIM * 32 + 255) / 256, 256>>>(W1, b1);
    kMV2<<<(DIM * 32 + 255) / 256, 256>>>(W2, b2, out);
}

// round 7
// speedup vs baseline: 1.3147x; 1.3147x over previous
#include <cuda_runtime.h>

#define N_NODES 10000
#define N_EDGES 160000
#define DIM     1280
#define D4      (DIM / 4)   // 320 float4 per row
#define NTHREADS 320

// ---- scratch (device globals; zero at load, self-reset at end of launch) ----
__device__ float g_outw[N_NODES];
__device__ float g_q[N_NODES];
__device__ float g_ew[N_EDGES];   // overwritten every launch
__device__ float g_Csum;          // sum of all edge weights (C = N + Csum)
__device__ float g_S1[DIM];       // sum_s coef[s]*h0[s]
__device__ float g_msum[DIM];     // sum_s h0[s]
__device__ float g_v1[DIM];       // layer-1 weighted-mean output

// ---- software grid barrier ----
__device__ unsigned g_cnt = 0;
__device__ volatile unsigned g_gen = 0;

__device__ __forceinline__ void grid_barrier() {
    __syncthreads();
    if (threadIdx.x == 0) {
        __threadfence();
        unsigned gen = g_gen;
        if (atomicAdd(&g_cnt, 1u) == gridDim.x - 1u) {
            g_cnt = 0;
            __threadfence();
            g_gen = gen + 1u;
        } else {
            while (g_gen == gen) { __nanosleep(64); }
        }
        __threadfence();
    }
    __syncthreads();
}

__device__ __forceinline__ float edge_w(float x) {
    return 1.0f / (x * x + 1e-6f);
}
__device__ __forceinline__ void fma4(float4& a, float c, const float4& v) {
    a.x = fmaf(c, v.x, a.x); a.y = fmaf(c, v.y, a.y);
    a.z = fmaf(c, v.z, a.z); a.w = fmaf(c, v.w, a.w);
}
__device__ __forceinline__ void add4(float4& a, const float4& v) {
    a.x += v.x; a.y += v.y; a.z += v.z; a.w += v.w;
}

__global__ void __launch_bounds__(NTHREADS, 1)
fused_kernel(const float* __restrict__ node,
             const float* __restrict__ ef,
             const int*   __restrict__ src,
             const int*   __restrict__ dst,
             const float* __restrict__ W1,
             const float* __restrict__ b1,
             const float* __restrict__ W2,
             const float* __restrict__ b2,
             float*       __restrict__ out) {
    const int tid = blockIdx.x * blockDim.x + threadIdx.x;
    const int nt  = gridDim.x * blockDim.x;
    const int lane = threadIdx.x & 31;
    const int warp_in_blk = threadIdx.x >> 5;   // 0..9
    const int gwarp = tid >> 5;
    const int nwarps = nt >> 5;
    __shared__ float sh[32];

    // ---------- Phase 1: ew cache, outw[src] += ew, Csum += ew ----------
    {
        float csum_local = 0.f;
        for (int e = tid; e < N_EDGES; e += nt) {
            float w = edge_w(ef[e]);
            g_ew[e] = w;
            csum_local += w;
            atomicAdd(&g_outw[src[e]], w);
        }
        #pragma unroll
        for (int o = 16; o; o >>= 1)
            csum_local += __shfl_down_sync(0xffffffffu, csum_local, o);
        if (threadIdx.x < 32) sh[threadIdx.x] = 0.f;
        __syncthreads();
        if (lane == 0) sh[warp_in_blk] = csum_local;
        __syncthreads();
        if (threadIdx.x < 32) {                  // full warp 0 participates
            float v = sh[threadIdx.x];
            #pragma unroll
            for (int o = 16; o; o >>= 1) v += __shfl_down_sync(0xffffffffu, v, o);
            if (threadIdx.x == 0) atomicAdd(&g_Csum, v);
        }
    }
    grid_barrier();

    // ---------- Phase 2: q[src] += ew*(1+outw[dst]) ----------
    for (int e = tid; e < N_EDGES; e += nt) {
        float w = g_ew[e];
        atomicAdd(&g_q[src[e]], w * (1.0f + g_outw[dst[e]]));
    }
    grid_barrier();

    // ---------- Phase 3: weighted + plain column sums over node_feat0 ----------
    {
        const int t = threadIdx.x;               // one float4 column slice
        const int stride = gridDim.x;
        const float4* __restrict__ h4 = (const float4*)node;
        float4 aw = make_float4(0.f, 0.f, 0.f, 0.f);
        float4 as = make_float4(0.f, 0.f, 0.f, 0.f);
        int s = blockIdx.x;
        for (; s + 3 * stride < N_NODES; s += 4 * stride) {
            int s0 = s, s1 = s + stride, s2 = s + 2 * stride, s3 = s + 3 * stride;
            float c0 = 1.0f + __ldg(&g_outw[s0]) + __ldg(&g_q[s0]);
            float c1 = 1.0f + __ldg(&g_outw[s1]) + __ldg(&g_q[s1]);
            float c2 = 1.0f + __ldg(&g_outw[s2]) + __ldg(&g_q[s2]);
            float c3 = 1.0f + __ldg(&g_outw[s3]) + __ldg(&g_q[s3]);
            float4 v0 = __ldg(&h4[(long)s0 * D4 + t]);
            float4 v1 = __ldg(&h4[(long)s1 * D4 + t]);
            float4 v2 = __ldg(&h4[(long)s2 * D4 + t]);
            float4 v3 = __ldg(&h4[(long)s3 * D4 + t]);
            fma4(aw, c0, v0); add4(as, v0);
            fma4(aw, c1, v1); add4(as, v1);
            fma4(aw, c2, v2); add4(as, v2);
            fma4(aw, c3, v3); add4(as, v3);
        }
        for (; s < N_NODES; s += stride) {
            float c = 1.0f + __ldg(&g_outw[s]) + __ldg(&g_q[s]);
            float4 v = __ldg(&h4[(long)s * D4 + t]);
            fma4(aw, c, v); add4(as, v);
        }
        int d = 4 * t;
        atomicAdd(&g_S1[d + 0], aw.x); atomicAdd(&g_S1[d + 1], aw.y);
        atomicAdd(&g_S1[d + 2], aw.z); atomicAdd(&g_S1[d + 3], aw.w);
        atomicAdd(&g_msum[d + 0], as.x); atomicAdd(&g_msum[d + 1], as.y);
        atomicAdd(&g_msum[d + 2], as.z); atomicAdd(&g_msum[d + 3], as.w);
    }
    grid_barrier();

    // ---------- Phase 4: v1 = (S1/N) @ W1^T + (C/N)*b1 ----------
    {
        const float invN = 1.0f / (float)N_NODES;
        const float C = (float)N_NODES + g_Csum;
        for (int row = gwarp; row < DIM; row += nwarps) {
            const float4* __restrict__ wr = (const float4*)(W1 + (long)row * DIM);
            const float4* __restrict__ s1 = (const float4*)g_S1;
            float acc = 0.f;
            #pragma unroll
            for (int j = lane; j < D4; j += 32) {
                float4 w = __ldg(&wr[j]);
                float4 s = s1[j];
                acc += w.x * s.x + w.y * s.y + w.z * s.z + w.w * s.w;
            }
            #pragma unroll
            for (int o = 16; o; o >>= 1) acc += __shfl_down_sync(0xffffffffu, acc, o);
            if (lane == 0)
                g_v1[row] = acc * invN + C * invN * __ldg(&b1[row]);
        }
    }
    grid_barrier();

    // ---------- Phase 5: out = v1 @ W2^T + b2 + msum/N ; reset scratch ----------
    {
        const float invN = 1.0f / (float)N_NODES;
        for (int row = gwarp; row < DIM; row += nwarps) {
            const float4* __restrict__ wr = (const float4*)(W2 + (long)row * DIM);
            const float4* __restrict__ v1 = (const float4*)g_v1;
            float acc = 0.f;
            #pragma unroll
            for (int j = lane; j < D4; j += 32) {
                float4 w = __ldg(&wr[j]);
                float4 v = v1[j];
                acc += w.x * v.x + w.y * v.y + w.z * v.z + w.w * v.w;
            }
            #pragma unroll
            for (int o = 16; o; o >>= 1) acc += __shfl_down_sync(0xffffffffu, acc, o);
            if (lane == 0) {
                out[row] = acc + __ldg(&b2[row]) + g_msum[row] * invN;
                g_msum[row] = 0.f;               // reset after final read
                g_S1[row]   = 0.f;               // consumed in phase 4
            }
        }
        for (int s = tid; s < N_NODES; s += nt) { g_outw[s] = 0.f; g_q[s] = 0.f; }
        if (tid == 0) g_Csum = 0.f;
    }
}

extern "C" void kernel_launch(void* const* d_in, const int* in_sizes, int n_in,
                              void* d_out, int out_size) {
    const float* node = (const float*)d_in[0];   // [N, D]
    const float* ef   = (const float*)d_in[1];   // [E]
    const int*   ei   = (const int*)  d_in[2];   // [2, E]
    const float* W1   = (const float*)d_in[3];
    const float* b1   = (const float*)d_in[4];
    const float* W2   = (const float*)d_in[5];
    const float* b2   = (const float*)d_in[6];
    float* out = (float*)d_out;

    const int* src = ei;
    const int* dst = ei + N_EDGES;

    // Grid barrier safety: exactly 1 block/SM, all simultaneously resident.
    int dev = 0, sms = 148, maxb = 1;
    cudaGetDevice(&dev);
    cudaDeviceGetAttribute(&sms, cudaDevAttrMultiProcessorCount, dev);
    cudaOccupancyMaxActiveBlocksPerMultiprocessor(&maxb, fused_kernel, NTHREADS, 0);
    int grid = (maxb >= 1) ? sms : 1;
    if (grid < 1) grid = 1;

    fused_kernel<<<grid, NTHREADS>>>(node, ef, src, dst, W1, b1, W2, b2, out);
}

// round 9
// speedup vs baseline: 1.4706x; 1.1186x over previous
#include <cuda_runtime.h>

#define N_NODES 10000
#define N_EDGES 160000
#define DIM     1280
#define D4      (DIM / 4)     // 320 float4 per row
#define CSLICES 320           // column slices in phase 3
#define SUBROWS 2
#define NTHREADS (CSLICES * SUBROWS)   // 640

// ---- scratch (device globals; zero at load, self-reset at end of launch) ----
__device__ float g_outw[N_NODES];
__device__ float g_q[N_NODES];
__device__ float g_Csum;          // sum of all edge weights (C = N + Csum)
__device__ float g_S1[DIM];       // sum_s coef[s]*h0[s]
__device__ float g_msum[DIM];     // sum_s h0[s]
__device__ float g_v1[DIM];       // layer-1 weighted-mean output

// ---- software grid barrier ----
__device__ unsigned g_cnt = 0;
__device__ volatile unsigned g_gen = 0;

__device__ __forceinline__ void grid_barrier() {
    __syncthreads();
    if (threadIdx.x == 0) {
        __threadfence();
        unsigned gen = g_gen;
        if (atomicAdd(&g_cnt, 1u) == gridDim.x - 1u) {
            g_cnt = 0;
            __threadfence();
            g_gen = gen + 1u;
        } else {
            while (g_gen == gen) { __nanosleep(64); }
        }
        __threadfence();
    }
    __syncthreads();
}

__device__ __forceinline__ float edge_w(float x) {
    return 1.0f / (x * x + 1e-6f);
}
__device__ __forceinline__ void fma4(float4& a, float c, const float4& v) {
    a.x = fmaf(c, v.x, a.x); a.y = fmaf(c, v.y, a.y);
    a.z = fmaf(c, v.z, a.z); a.w = fmaf(c, v.w, a.w);
}
__device__ __forceinline__ void add4(float4& a, const float4& v) {
    a.x += v.x; a.y += v.y; a.z += v.z; a.w += v.w;
}

__global__ void __launch_bounds__(NTHREADS, 1)
fused_kernel(const float* __restrict__ node,
             const float* __restrict__ ef,
             const int*   __restrict__ src,
             const int*   __restrict__ dst,
             const float* __restrict__ W1,
             const float* __restrict__ b1,
             const float* __restrict__ W2,
             const float* __restrict__ b2,
             float*       __restrict__ out) {
    const int tid = blockIdx.x * blockDim.x + threadIdx.x;
    const int nt  = gridDim.x * blockDim.x;
    const int lane = threadIdx.x & 31;
    const int warp_in_blk = threadIdx.x >> 5;        // 0..19
    const int nwarps_tot = (blockDim.x >> 5) * gridDim.x;

    __shared__ float sh[32];
    __shared__ float s1sh[DIM];
    __shared__ float mssh[DIM];

    // ---------- Phase 1: outw[src] += ew ; Csum += ew ----------
    {
        float csum_local = 0.f;
        for (int e = tid; e < N_EDGES; e += nt) {
            float w = edge_w(__ldg(&ef[e]));
            csum_local += w;
            atomicAdd(&g_outw[__ldg(&src[e])], w);
        }
        #pragma unroll
        for (int o = 16; o; o >>= 1)
            csum_local += __shfl_down_sync(0xffffffffu, csum_local, o);
        if (threadIdx.x < 32) sh[threadIdx.x] = 0.f;
        __syncthreads();
        if (lane == 0) sh[warp_in_blk] = csum_local;
        __syncthreads();
        if (threadIdx.x < 32) {
            float v = sh[threadIdx.x];
            #pragma unroll
            for (int o = 16; o; o >>= 1) v += __shfl_down_sync(0xffffffffu, v, o);
            if (threadIdx.x == 0) atomicAdd(&g_Csum, v);
        }
    }
    grid_barrier();

    // ---------- Phase 2: q[src] += ew*(1+outw[dst]) ----------
    for (int e = tid; e < N_EDGES; e += nt) {
        float w = edge_w(__ldg(&ef[e]));             // recompute; ef is L2-hot
        atomicAdd(&g_q[__ldg(&src[e])], w * (1.0f + g_outw[__ldg(&dst[e])]));
    }
    grid_barrier();

    // ---------- Phase 3: weighted + plain column sums over node_feat0 ----------
    {
        const int sub = threadIdx.x / CSLICES;       // 0..1
        const int t   = threadIdx.x - sub * CSLICES; // 0..319
        const int stride = gridDim.x * SUBROWS;
        const float4* __restrict__ h4 = (const float4*)node;
        float4 aw = make_float4(0.f, 0.f, 0.f, 0.f);
        float4 as = make_float4(0.f, 0.f, 0.f, 0.f);
        int s = blockIdx.x * SUBROWS + sub;
        for (; s + 3 * stride < N_NODES; s += 4 * stride) {
            int s0 = s, s1 = s + stride, s2 = s + 2 * stride, s3 = s + 3 * stride;
            float c0 = 1.0f + __ldg(&g_outw[s0]) + __ldg(&g_q[s0]);
            float c1 = 1.0f + __ldg(&g_outw[s1]) + __ldg(&g_q[s1]);
            float c2 = 1.0f + __ldg(&g_outw[s2]) + __ldg(&g_q[s2]);
            float c3 = 1.0f + __ldg(&g_outw[s3]) + __ldg(&g_q[s3]);
            float4 v0 = __ldg(&h4[(long)s0 * D4 + t]);
            float4 v1 = __ldg(&h4[(long)s1 * D4 + t]);
            float4 v2 = __ldg(&h4[(long)s2 * D4 + t]);
            float4 v3 = __ldg(&h4[(long)s3 * D4 + t]);
            fma4(aw, c0, v0); add4(as, v0);
            fma4(aw, c1, v1); add4(as, v1);
            fma4(aw, c2, v2); add4(as, v2);
            fma4(aw, c3, v3); add4(as, v3);
        }
        for (; s < N_NODES; s += stride) {
            float c = 1.0f + __ldg(&g_outw[s]) + __ldg(&g_q[s]);
            float4 v = __ldg(&h4[(long)s * D4 + t]);
            fma4(aw, c, v); add4(as, v);
        }
        // block-level reduction in shared, then one global atomic per element
        for (int i = threadIdx.x; i < DIM; i += blockDim.x) {
            s1sh[i] = 0.f; mssh[i] = 0.f;
        }
        __syncthreads();
        int d = 4 * t;
        atomicAdd(&s1sh[d + 0], aw.x); atomicAdd(&s1sh[d + 1], aw.y);
        atomicAdd(&s1sh[d + 2], aw.z); atomicAdd(&s1sh[d + 3], aw.w);
        atomicAdd(&mssh[d + 0], as.x); atomicAdd(&mssh[d + 1], as.y);
        atomicAdd(&mssh[d + 2], as.z); atomicAdd(&mssh[d + 3], as.w);
        __syncthreads();
        // vectorized flush: 320 float4 per array, threads 0..319 / 320..639
        if (threadIdx.x < CSLICES) {
            float4 v = ((const float4*)s1sh)[threadIdx.x];
            int d2 = 4 * threadIdx.x;
            atomicAdd(&g_S1[d2 + 0], v.x); atomicAdd(&g_S1[d2 + 1], v.y);
            atomicAdd(&g_S1[d2 + 2], v.z); atomicAdd(&g_S1[d2 + 3], v.w);
        } else {
            int j = threadIdx.x - CSLICES;
            float4 v = ((const float4*)mssh)[j];
            int d2 = 4 * j;
            atomicAdd(&g_msum[d2 + 0], v.x); atomicAdd(&g_msum[d2 + 1], v.y);
            atomicAdd(&g_msum[d2 + 2], v.z); atomicAdd(&g_msum[d2 + 3], v.w);
        }
    }
    grid_barrier();

    // ---------- Phase 4: v1 = (S1/N) @ W1^T + (C/N)*b1 ----------
    // row mapping spreads active warps across ALL blocks/SMs
    {
        const float invN = 1.0f / (float)N_NODES;
        const float C = (float)N_NODES + g_Csum;
        for (int row = warp_in_blk * gridDim.x + blockIdx.x; row < DIM;
             row += nwarps_tot) {
            const float4* __restrict__ wr = (const float4*)(W1 + (long)row * DIM);
            const float4* __restrict__ s1 = (const float4*)g_S1;
            float acc = 0.f;
            #pragma unroll
            for (int j = lane; j < D4; j += 32) {
                float4 w = __ldg(&wr[j]);
                float4 s = s1[j];
                acc += w.x * s.x + w.y * s.y + w.z * s.z + w.w * s.w;
            }
            #pragma unroll
            for (int o = 16; o; o >>= 1) acc += __shfl_down_sync(0xffffffffu, acc, o);
            if (lane == 0)
                g_v1[row] = acc * invN + C * invN * __ldg(&b1[row]);
        }
    }
    grid_barrier();

    // ---------- Phase 5: out = v1 @ W2^T + b2 + msum/N ; reset scratch ----------
    {
        const float invN = 1.0f / (float)N_NODES;
        for (int row = warp_in_blk * gridDim.x + blockIdx.x; row < DIM;
             row += nwarps_tot) {
            const float4* __restrict__ wr = (const float4*)(W2 + (long)row * DIM);
            const float4* __restrict__ v1 = (const float4*)g_v1;
            float acc = 0.f;
            #pragma unroll
            for (int j = lane; j < D4; j += 32) {
                float4 w = __ldg(&wr[j]);
                float4 v = v1[j];
                acc += w.x * v.x + w.y * v.y + w.z * v.z + w.w * v.w;
            }
            #pragma unroll
            for (int o = 16; o; o >>= 1) acc += __shfl_down_sync(0xffffffffu, acc, o);
            if (lane == 0) {
                out[row] = acc + __ldg(&b2[row]) + g_msum[row] * invN;
                g_msum[row] = 0.f;               // reset after final read
                g_S1[row]   = 0.f;               // consumed in phase 4
            }
        }
        for (int s = tid; s < N_NODES; s += nt) { g_outw[s] = 0.f; g_q[s] = 0.f; }
        if (tid == 0) g_Csum = 0.f;
    }
}

extern "C" void kernel_launch(void* const* d_in, const int* in_sizes, int n_in,
                              void* d_out, int out_size) {
    const float* node = (const float*)d_in[0];   // [N, D]
    const float* ef   = (const float*)d_in[1];   // [E]
    const int*   ei   = (const int*)  d_in[2];   // [2, E]
    const float* W1   = (const float*)d_in[3];
    const float* b1   = (const float*)d_in[4];
    const float* W2   = (const float*)d_in[5];
    const float* b2   = (const float*)d_in[6];
    float* out = (float*)d_out;

    const int* src = ei;
    const int* dst = ei + N_EDGES;

    // Grid barrier safety: exactly 1 block/SM, all simultaneously resident.
    int dev = 0, sms = 148, maxb = 1;
    cudaGetDevice(&dev);
    cudaDeviceGetAttribute(&sms, cudaDevAttrMultiProcessorCount, dev);
    cudaOccupancyMaxActiveBlocksPerMultiprocessor(&maxb, fused_kernel, NTHREADS, 0);
    int grid = (maxb >= 1) ? sms : 1;
    if (grid < 1) grid = 1;

    fused_kernel<<<grid, NTHREADS>>>(node, ef, src, dst, W1, b1, W2, b2, out);
}

// round 10
// speedup vs baseline: 1.5326x; 1.0421x over previous
#include <cuda_runtime.h>

#define N_NODES 10000
#define N_EDGES 160000
#define DIM     1280
#define D4      (DIM / 4)     // 320 float4 per row
#define CSLICES 320           // column slices in phase 3
#define SUBROWS 2
#define NTHREADS (CSLICES * SUBROWS)   // 640, 20 warps/block (even => warp pairs stay in-block)

// ---- scratch (device globals; zero at load; resets staggered across phases) ----
__device__ float g_outw[N_NODES];
__device__ float g_q[N_NODES];
__device__ float g_Csum;          // sum of all edge weights (C = N + Csum)
__device__ float g_S1[DIM];       // sum_s coef[s]*h0[s]
__device__ float g_msum[DIM];     // sum_s h0[s]
__device__ float g_v1[DIM];       // layer-1 result (atomic-accumulated)

// ---- software grid barrier ----
__device__ unsigned g_cnt = 0;
__device__ volatile unsigned g_gen = 0;

__device__ __forceinline__ void grid_barrier() {
    __syncthreads();
    if (threadIdx.x == 0) {
        __threadfence();
        unsigned gen = g_gen;
        if (atomicAdd(&g_cnt, 1u) == gridDim.x - 1u) {
            g_cnt = 0;
            __threadfence();
            g_gen = gen + 1u;
        } else {
            while (g_gen == gen) { __nanosleep(64); }
        }
        __threadfence();
    }
    __syncthreads();
}

__device__ __forceinline__ float edge_w(float x) {
    return 1.0f / (x * x + 1e-6f);
}
__device__ __forceinline__ void fma4(float4& a, float c, const float4& v) {
    a.x = fmaf(c, v.x, a.x); a.y = fmaf(c, v.y, a.y);
    a.z = fmaf(c, v.z, a.z); a.w = fmaf(c, v.w, a.w);
}
__device__ __forceinline__ void add4(float4& a, const float4& v) {
    a.x += v.x; a.y += v.y; a.z += v.z; a.w += v.w;
}
__device__ __forceinline__ float dot4(const float4& a, const float4& b) {
    return a.x * b.x + a.y * b.y + a.z * b.z + a.w * b.w;
}

__global__ void __launch_bounds__(NTHREADS, 1)
fused_kernel(const float* __restrict__ node,
             const float* __restrict__ ef,
             const int*   __restrict__ src,
             const int*   __restrict__ dst,
             const float* __restrict__ W1,
             const float* __restrict__ b1,
             const float* __restrict__ W2,
             const float* __restrict__ b2,
             float*       __restrict__ out) {
    const int tid = blockIdx.x * blockDim.x + threadIdx.x;
    const int nt  = gridDim.x * blockDim.x;
    const int lane = threadIdx.x & 31;
    const int warp_in_blk = threadIdx.x >> 5;                  // 0..19
    const int gwarp = blockIdx.x * (blockDim.x >> 5) + warp_in_blk;

    __shared__ float sh[32];
    __shared__ float s1sh[DIM];
    __shared__ float mssh[DIM];

    // ---------- Phase 1: outw[src] += ew ; Csum += ew ; reset S1/msum/v1 ----------
    {
        // reset accumulators from the previous launch (first use is P3/P4; barriers order it)
        for (int i = tid; i < DIM; i += nt) {
            g_S1[i] = 0.f; g_msum[i] = 0.f; g_v1[i] = 0.f;
        }
        float csum_local = 0.f;
        for (int e = tid; e < N_EDGES; e += nt) {
            float w = edge_w(__ldg(&ef[e]));
            csum_local += w;
            atomicAdd(&g_outw[src[e]], w);
        }
        #pragma unroll
        for (int o = 16; o; o >>= 1)
            csum_local += __shfl_down_sync(0xffffffffu, csum_local, o);
        if (threadIdx.x < 32) sh[threadIdx.x] = 0.f;
        __syncthreads();
        if (lane == 0) sh[warp_in_blk] = csum_local;
        __syncthreads();
        if (threadIdx.x < 32) {
            float v = sh[threadIdx.x];
            #pragma unroll
            for (int o = 16; o; o >>= 1) v += __shfl_down_sync(0xffffffffu, v, o);
            if (threadIdx.x == 0) atomicAdd(&g_Csum, v);
        }
    }
    grid_barrier();

    // ---------- Phase 2: q[src] += ew*(1+outw[dst]) ----------
    for (int e = tid; e < N_EDGES; e += nt) {
        float w = edge_w(__ldg(&ef[e]));                       // ef/src L2-hot
        atomicAdd(&g_q[src[e]], w * (1.0f + g_outw[dst[e]]));
    }
    grid_barrier();

    // ---------- Phase 3: weighted + plain column sums over node_feat0 ----------
    {
        const int sub = threadIdx.x / CSLICES;                 // 0..1
        const int t   = threadIdx.x - sub * CSLICES;           // 0..319
        const int stride = gridDim.x * SUBROWS;
        const float4* __restrict__ h4 = (const float4*)node;
        float4 aw = make_float4(0.f, 0.f, 0.f, 0.f);
        float4 as = make_float4(0.f, 0.f, 0.f, 0.f);
        int s = blockIdx.x * SUBROWS + sub;
        for (; s + 3 * stride < N_NODES; s += 4 * stride) {
            int s0 = s, s1 = s + stride, s2 = s + 2 * stride, s3 = s + 3 * stride;
            float c0 = 1.0f + __ldg(&g_outw[s0]) + __ldg(&g_q[s0]);
            float c1 = 1.0f + __ldg(&g_outw[s1]) + __ldg(&g_q[s1]);
            float c2 = 1.0f + __ldg(&g_outw[s2]) + __ldg(&g_q[s2]);
            float c3 = 1.0f + __ldg(&g_outw[s3]) + __ldg(&g_q[s3]);
            float4 v0 = __ldg(&h4[(long)s0 * D4 + t]);
            float4 v1 = __ldg(&h4[(long)s1 * D4 + t]);
            float4 v2 = __ldg(&h4[(long)s2 * D4 + t]);
            float4 v3 = __ldg(&h4[(long)s3 * D4 + t]);
            fma4(aw, c0, v0); add4(as, v0);
            fma4(aw, c1, v1); add4(as, v1);
            fma4(aw, c2, v2); add4(as, v2);
            fma4(aw, c3, v3); add4(as, v3);
        }
        for (; s < N_NODES; s += stride) {
            float c = 1.0f + __ldg(&g_outw[s]) + __ldg(&g_q[s]);
            float4 v = __ldg(&h4[(long)s * D4 + t]);
            fma4(aw, c, v); add4(as, v);
        }
        // block-level reduction in shared, then vectorized global flush
        for (int i = threadIdx.x; i < DIM; i += blockDim.x) {
            s1sh[i] = 0.f; mssh[i] = 0.f;
        }
        __syncthreads();
        int d = 4 * t;
        atomicAdd(&s1sh[d + 0], aw.x); atomicAdd(&s1sh[d + 1], aw.y);
        atomicAdd(&s1sh[d + 2], aw.z); atomicAdd(&s1sh[d + 3], aw.w);
        atomicAdd(&mssh[d + 0], as.x); atomicAdd(&mssh[d + 1], as.y);
        atomicAdd(&mssh[d + 2], as.z); atomicAdd(&mssh[d + 3], as.w);
        __syncthreads();
        if (threadIdx.x < CSLICES) {
            float4 v = ((const float4*)s1sh)[threadIdx.x];
            int d2 = 4 * threadIdx.x;
            atomicAdd(&g_S1[d2 + 0], v.x); atomicAdd(&g_S1[d2 + 1], v.y);
            atomicAdd(&g_S1[d2 + 2], v.z); atomicAdd(&g_S1[d2 + 3], v.w);
        } else {
            int j = threadIdx.x - CSLICES;
            float4 v = ((const float4*)mssh)[j];
            int d2 = 4 * j;
            atomicAdd(&g_msum[d2 + 0], v.x); atomicAdd(&g_msum[d2 + 1], v.y);
            atomicAdd(&g_msum[d2 + 2], v.z); atomicAdd(&g_msum[d2 + 3], v.w);
        }
    }
    grid_barrier();

    // ---------- Phase 4: v1 += partial (2 warps/row, all-warp MLP) ----------
    // Also: zero out[] for P5's atomics; reset outw/q (P3 was last reader).
    {
        const float invN = 1.0f / (float)N_NODES;
        const float C = (float)N_NODES + g_Csum;
        const int row  = gwarp >> 1;                           // 0..1479
        const int half = gwarp & 1;
        for (int i = tid; i < DIM; i += nt) out[i] = 0.f;
        if (row < DIM) {
            const float4* __restrict__ wr = (const float4*)(W1 + (long)row * DIM);
            const float4* __restrict__ s1 = (const float4*)g_S1;
            const int base = half * (D4 / 2) + lane;           // 160*half + lane
            float acc = 0.f;
            #pragma unroll
            for (int k = 0; k < 5; k++) {
                int j = base + k * 32;
                acc += dot4(__ldg(&wr[j]), s1[j]);
            }
            #pragma unroll
            for (int o = 16; o; o >>= 1) acc += __shfl_down_sync(0xffffffffu, acc, o);
            if (lane == 0) {
                float contrib = acc * invN;
                if (half == 0) contrib += C * invN * __ldg(&b1[row]);
                atomicAdd(&g_v1[row], contrib);
            }
        }
        for (int s2 = tid; s2 < N_NODES; s2 += nt) { g_outw[s2] = 0.f; g_q[s2] = 0.f; }
    }
    grid_barrier();

    // ---------- Phase 5: out += partial + b2 + msum/N ; reset Csum ----------
    {
        const float invN = 1.0f / (float)N_NODES;
        const int row  = gwarp >> 1;
        const int half = gwarp & 1;
        if (row < DIM) {
            const float4* __restrict__ wr = (const float4*)(W2 + (long)row * DIM);
            const float4* __restrict__ v1 = (const float4*)g_v1;
            const int base = half * (D4 / 2) + lane;
            float acc = 0.f;
            #pragma unroll
            for (int k = 0; k < 5; k++) {
                int j = base + k * 32;
                acc += dot4(__ldg(&wr[j]), v1[j]);
            }
            #pragma unroll
            for (int o = 16; o; o >>= 1) acc += __shfl_down_sync(0xffffffffu, acc, o);
            if (lane == 0) {
                float contrib = acc;
                if (half == 0)
                    contrib += __ldg(&b2[row]) + g_msum[row] * invN;
                atomicAdd(&out[row], contrib);
            }
        }
        if (tid == 0) g_Csum = 0.f;
    }
}

extern "C" void kernel_launch(void* const* d_in, const int* in_sizes, int n_in,
                              void* d_out, int out_size) {
    const float* node = (const float*)d_in[0];   // [N, D]
    const float* ef   = (const float*)d_in[1];   // [E]
    const int*   ei   = (const int*)  d_in[2];   // [2, E]
    const float* W1   = (const float*)d_in[3];
    const float* b1   = (const float*)d_in[4];
    const float* W2   = (const float*)d_in[5];
    const float* b2   = (const float*)d_in[6];
    float* out = (float*)d_out;

    const int* src = ei;
    const int* dst = ei + N_EDGES;

    // Grid barrier safety: exactly 1 block/SM, all simultaneously resident.
    int dev = 0, sms = 148, maxb = 1;
    cudaGetDevice(&dev);
    cudaDeviceGetAttribute(&sms, cudaDevAttrMultiProcessorCount, dev);
    cudaOccupancyMaxActiveBlocksPerMultiprocessor(&maxb, fused_kernel, NTHREADS, 0);
    int grid = (maxb >= 1) ? sms : 1;
    if (grid < 1) grid = 1;

    fused_kernel<<<grid, NTHREADS>>>(node, ef, src, dst, W1, b1, W2, b2, out);
}